// round 11
// baseline (speedup 1.0000x reference)
#include <cuda_runtime.h>
#include <cuda_bf16.h>
#include <cstdint>

// Problem constants: N=512, A=1024, B=64, C=16
#define NN   512
#define AA   1024
#define BB   64
#define CC   16
#define OUTW (AA + BB)   // 1088

#define NGRP   16            // row groups of 32
#define GSZ    32
#define NTILES (NGRP * (NGRP + 1) / 2)   // 136

#define LOG2E 1.44269504088896340736f

// ---------------- device scratch ----------------
// M (pre-scaled by log2e) in bf16x2: g_Mb[row*512 + b*8 + c2]
__device__ uint32_t g_Mb[NN * 512];

// ---------------- helpers ----------------
__device__ __forceinline__ uint32_t smem_u32(const void* p) {
    uint32_t a;
    asm("{ .reg .u64 t; cvta.to.shared.u64 t, %1; cvt.u32.u64 %0, t; }" : "=r"(a) : "l"(p));
    return a;
}
#define LDMATRIX_X4(r0, r1, r2, r3, addr) \
    asm volatile("ldmatrix.sync.aligned.m8n8.x4.shared.b16 {%0,%1,%2,%3}, [%4];" \
        : "=r"(r0), "=r"(r1), "=r"(r2), "=r"(r3) : "r"(addr))
#define LDMATRIX_X4_T(r0, r1, r2, r3, addr) \
    asm volatile("ldmatrix.sync.aligned.m8n8.x4.trans.shared.b16 {%0,%1,%2,%3}, [%4];" \
        : "=r"(r0), "=r"(r1), "=r"(r2), "=r"(r3) : "r"(addr))

__device__ __forceinline__ void mma_bf16(float d[4], const uint32_t a[4], const uint32_t b[2]) {
    asm volatile(
        "mma.sync.aligned.m16n8k16.row.col.f32.bf16.bf16.f32 "
        "{%0,%1,%2,%3}, {%4,%5,%6,%7}, {%8,%9}, {%0,%1,%2,%3};"
        : "+f"(d[0]), "+f"(d[1]), "+f"(d[2]), "+f"(d[3])
        : "r"(a[0]), "r"(a[1]), "r"(a[2]), "r"(a[3]), "r"(b[0]), "r"(b[1]));
}

__device__ __forceinline__ __nv_bfloat162 u2b(uint32_t u) {
    return *reinterpret_cast<__nv_bfloat162*>(&u);
}
__device__ __forceinline__ uint32_t b2u(__nv_bfloat162 v) {
    return *reinterpret_cast<uint32_t*>(&v);
}
__device__ __forceinline__ float ex2(float v) {
    float r; asm("ex2.approx.f32 %0, %1;" : "=f"(r) : "f"(v)); return r;
}

// convert 8 consecutive f32 (two float4) to packed bf16 uint4, with scale
__device__ __forceinline__ uint4 cvt8(const float* p, float s) {
    float4 a = *reinterpret_cast<const float4*>(p);
    float4 b = *reinterpret_cast<const float4*>(p + 4);
    __nv_bfloat162 p0 = __float22bfloat162_rn(make_float2(a.x * s, a.y * s));
    __nv_bfloat162 p1 = __float22bfloat162_rn(make_float2(a.z * s, a.w * s));
    __nv_bfloat162 p2 = __float22bfloat162_rn(make_float2(b.x * s, b.y * s));
    __nv_bfloat162 p3 = __float22bfloat162_rn(make_float2(b.z * s, b.w * s));
    uint4 o; o.x = b2u(p0); o.y = b2u(p1); o.z = b2u(p2); o.w = b2u(p3);
    return o;
}

// -(L1 over 16 bf16 components held as 8 bf16x2 regs); exact lo/hi extraction.
__device__ __forceinline__ float l1_neg(const uint32_t* mj, const uint32_t* mi) {
    __nv_bfloat162 d0 = __habs2(__hsub2(u2b(mj[0]), u2b(mi[0])));
    __nv_bfloat162 d1 = __habs2(__hsub2(u2b(mj[1]), u2b(mi[1])));
    __nv_bfloat162 d2 = __habs2(__hsub2(u2b(mj[2]), u2b(mi[2])));
    __nv_bfloat162 d3 = __habs2(__hsub2(u2b(mj[3]), u2b(mi[3])));
    __nv_bfloat162 d4 = __habs2(__hsub2(u2b(mj[4]), u2b(mi[4])));
    __nv_bfloat162 d5 = __habs2(__hsub2(u2b(mj[5]), u2b(mi[5])));
    __nv_bfloat162 d6 = __habs2(__hsub2(u2b(mj[6]), u2b(mi[6])));
    __nv_bfloat162 d7 = __habs2(__hsub2(u2b(mj[7]), u2b(mi[7])));
    __nv_bfloat162 s = __hadd2(__hadd2(__hadd2(d0, d1), __hadd2(d2, d3)),
                               __hadd2(__hadd2(d4, d5), __hadd2(d6, d7)));
    uint32_t u = b2u(s);
    float lo = __uint_as_float(u << 16);          // bf16 -> f32 zero-extension: exact
    float hi = __uint_as_float(u & 0xFFFF0000u);
    return (-lo) - hi;                            // FADD with neg modifiers
}

// ---------------------------------------------------------------------------
// Fused GEMM: copies x -> out, inits out tail to -1, computes
// M = (x * W*log2e) in bf16 via mma.sync with inline f32->bf16 staging.
// Block 64x64, 128 threads (4 warps 2x2), K chunked by 64, swizzled smem,
// register prefetch. A: x row-major [m][k]; B: W native [k][n] via
// ldmatrix.x4.trans. Epilogue -> bf16 g_Mb.
// ---------------------------------------------------------------------------
#define BK 64
#define NCH (AA / BK)   // 16

__global__ __launch_bounds__(128)
void gemm_fused_kernel(const float* __restrict__ x, const float* __restrict__ W,
                       float* __restrict__ out) {
    __shared__ __align__(1024) __nv_bfloat16 sA[64 * BK];   // 8 KB  [m-row][k]
    __shared__ __align__(1024) __nv_bfloat16 sB[64 * BK];   // 8 KB  [k-row][n]

    const int tid = threadIdx.x;
    const int wid = tid >> 5;
    const int l   = tid & 31;
    const int mw  = wid & 1;
    const int nw  = wid >> 1;
    const int row0 = blockIdx.y * 64;
    const int col0 = blockIdx.x * 64;

    // ---- fused x -> out copy (2 MB, 8 float4/thread) + tail init ----
    {
        const int bid = blockIdx.y * 16 + blockIdx.x;   // 0..127
        const int gt  = bid * 128 + tid;                // 0..16383
#pragma unroll
        for (int w = 0; w < 8; w++) {
            int idx = gt + w * 16384;                   // float4 idx 0..131071
            int row = idx >> 8;
            int c4  = idx & 255;
            float4 v = reinterpret_cast<const float4*>(x)[idx];
            *reinterpret_cast<float4*>(out + (size_t)row * OUTW + c4 * 4) = v;
        }
#pragma unroll
        for (int w = 0; w < 2; w++) {
            int idx = gt * 2 + w;                       // 0..32767
            int i = idx >> 6, b = idx & 63;
            out[(size_t)i * OUTW + AA + b] = -1.0f;
        }
    }

    const uint32_t sA_addr = smem_u32(sA);
    const uint32_t sB_addr = smem_u32(sB);

    float acc[2][4][4];
#pragma unroll
    for (int mt = 0; mt < 2; mt++)
#pragma unroll
        for (int nt = 0; nt < 4; nt++)
#pragma unroll
            for (int e = 0; e < 4; e++) acc[mt][nt][e] = 0.0f;

    // staging roles: seg s: ch = tid + s*128, r = ch>>3 (row), u = ch&7 (16B unit)
    const int sr = tid >> 3;          // base row for this thread (segments add 16)
    const int su = tid & 7;

    uint4 pa[4], pb[4];
#pragma unroll
    for (int s = 0; s < 4; s++) {
        int r = sr + s * 16;
        pa[s] = cvt8(x + (size_t)(row0 + r) * AA + su * 8, 1.0f);
        pb[s] = cvt8(W + (size_t)r * AA + col0 + su * 8, LOG2E);
    }

    const int aRow0 = ((l >> 3) & 1) * 8 + (l & 7) + mw * 32;
    const int aKsel = (l >> 4);
    const int bRowL = ((l >> 3) & 1) * 8 + (l & 7);   // k-row within 16-step
    const int bUsel = (l >> 4);                        // n 16B-unit selector
    const int swz   = (l & 7);

    for (int c = 0; c < NCH; c++) {
#pragma unroll
        for (int s = 0; s < 4; s++) {
            int r = sr + s * 16;
            uint32_t off = (uint32_t)(r * 128 + ((su ^ (r & 7)) << 4));
            *reinterpret_cast<uint4*>(reinterpret_cast<char*>(sA) + off) = pa[s];
            *reinterpret_cast<uint4*>(reinterpret_cast<char*>(sB) + off) = pb[s];
        }
        __syncthreads();

        if (c + 1 < NCH) {
            int k0 = (c + 1) * BK;
#pragma unroll
            for (int s = 0; s < 4; s++) {
                int r = sr + s * 16;
                pa[s] = cvt8(x + (size_t)(row0 + r) * AA + k0 + su * 8, 1.0f);
                pb[s] = cvt8(W + (size_t)(k0 + r) * AA + col0 + su * 8, LOG2E);
            }
        }

#pragma unroll
        for (int ks = 0; ks < 4; ks++) {
            uint32_t af[2][4], bf[4][2];
#pragma unroll
            for (int mt = 0; mt < 2; mt++) {
                int row = aRow0 + mt * 16;
                uint32_t u = (uint32_t)(ks * 2 + aKsel);
                uint32_t addr = sA_addr + (uint32_t)(row * 128) + (((u ^ swz)) << 4);
                LDMATRIX_X4(af[mt][0], af[mt][1], af[mt][2], af[mt][3], addr);
            }
#pragma unroll
            for (int h = 0; h < 2; h++) {
                int row = ks * 16 + bRowL;
                uint32_t u = (uint32_t)(nw * 4 + h * 2 + bUsel);
                uint32_t addr = sB_addr + (uint32_t)(row * 128) + (((u ^ (row & 7))) << 4);
                uint32_t r0, r1, r2, r3;
                LDMATRIX_X4_T(r0, r1, r2, r3, addr);
                bf[h * 2 + 0][0] = r0; bf[h * 2 + 0][1] = r1;
                bf[h * 2 + 1][0] = r2; bf[h * 2 + 1][1] = r3;
            }
#pragma unroll
            for (int mt = 0; mt < 2; mt++)
#pragma unroll
                for (int nt = 0; nt < 4; nt++)
                    mma_bf16(acc[mt][nt], af[mt], bf[nt]);
        }
        __syncthreads();
    }

    // Epilogue: bf16x2 into pairwise layout g_Mb[row*512 + b*8 + c2]
    const int g = l >> 2;
    const int cc2 = (l & 3) * 2;
#pragma unroll
    for (int mt = 0; mt < 2; mt++) {
#pragma unroll
        for (int nt = 0; nt < 4; nt++) {
            int gcol = col0 + nw * 32 + nt * 8 + cc2;
            int b  = gcol >> 4;
            int c2 = (gcol & 15) >> 1;
            int rowA = row0 + mw * 32 + mt * 16 + g;
            __nv_bfloat162 v0 = __float22bfloat162_rn(
                make_float2(acc[mt][nt][0], acc[mt][nt][1]));
            __nv_bfloat162 v1 = __float22bfloat162_rn(
                make_float2(acc[mt][nt][2], acc[mt][nt][3]));
            g_Mb[(size_t)rowA * 512 + b * 8 + c2]       = b2u(v0);
            g_Mb[(size_t)(rowA + 8) * 512 + b * 8 + c2] = b2u(v1);
        }
    }
}

// ---------------------------------------------------------------------------
// Pairwise, triangular tiles over 16 groups of 32 rows. 136 blocks x 512 thr
// (single co-resident wave). Thread (b = t&63, isp = t>>6 in 0..7): owns
// 4 i-rows, loops 32 j-rows (prefetch depth 2). Results atomically added
// straight into out[:,1024:] (pre-initialized to -1 by the GEMM kernel).
// ---------------------------------------------------------------------------
__global__ __launch_bounds__(512)
void pairwise_kernel(float* __restrict__ out) {
    const int t   = threadIdx.x;
    const int b   = t & 63;
    const int isp = t >> 6;        // 0..7

    // decode triangular tile: offset(g) = g*(33-g)/2 for NGRP=16
    int tt = blockIdx.x;
    int gi = 0;
#pragma unroll
    for (int g = 1; g < NGRP; g++)
        if ((g * (2 * NGRP + 1 - g)) / 2 <= tt) gi = g;
    int gj = gi + (tt - (gi * (2 * NGRP + 1 - gi)) / 2);

    const int i0 = gi * GSZ + isp * 4;
    const int j0 = gj * GSZ;

    __shared__ float red[16][8][BB];   // 32 KB (half of the j-group at a time)

    const uint4* Mb4 = reinterpret_cast<const uint4*>(g_Mb);

    // load 4 i-rows (8 u32 each)
    uint32_t mi[4][8];
#pragma unroll
    for (int k = 0; k < 4; k++) {
        uint4 v0 = Mb4[(size_t)(i0 + k) * 128 + b * 2];
        uint4 v1 = Mb4[(size_t)(i0 + k) * 128 + b * 2 + 1];
        mi[k][0] = v0.x; mi[k][1] = v0.y; mi[k][2] = v0.z; mi[k][3] = v0.w;
        mi[k][4] = v1.x; mi[k][5] = v1.y; mi[k][6] = v1.z; mi[k][7] = v1.w;
    }

    float acc_i[4] = {0.f, 0.f, 0.f, 0.f};

    // prefetch depth 2 on j-rows
    uint32_t jb[2][8];
#pragma unroll
    for (int p = 0; p < 2; p++) {
        uint4 v0 = Mb4[(size_t)(j0 + p) * 128 + b * 2];
        uint4 v1 = Mb4[(size_t)(j0 + p) * 128 + b * 2 + 1];
        jb[p][0] = v0.x; jb[p][1] = v0.y; jb[p][2] = v0.z; jb[p][3] = v0.w;
        jb[p][4] = v1.x; jb[p][5] = v1.y; jb[p][6] = v1.z; jb[p][7] = v1.w;
    }

    for (int half = 0; half < 2; half++) {
#pragma unroll
        for (int jj = 0; jj < 16; jj++) {
            const int jg = half * 16 + jj;
            uint32_t mj[8];
#pragma unroll
            for (int c = 0; c < 8; c++) mj[c] = jb[jg & 1][c];
            if (jg + 2 < GSZ) {
                uint4 v0 = Mb4[(size_t)(j0 + jg + 2) * 128 + b * 2];
                uint4 v1 = Mb4[(size_t)(j0 + jg + 2) * 128 + b * 2 + 1];
                jb[jg & 1][0] = v0.x; jb[jg & 1][1] = v0.y;
                jb[jg & 1][2] = v0.z; jb[jg & 1][3] = v0.w;
                jb[jg & 1][4] = v1.x; jb[jg & 1][5] = v1.y;
                jb[jg & 1][6] = v1.z; jb[jg & 1][7] = v1.w;
            }

            float e0 = ex2(l1_neg(mj, mi[0]));
            float e1 = ex2(l1_neg(mj, mi[1]));
            float e2 = ex2(l1_neg(mj, mi[2]));
            float e3 = ex2(l1_neg(mj, mi[3]));
            acc_i[0] += e0; acc_i[1] += e1; acc_i[2] += e2; acc_i[3] += e3;
            red[jj][isp][b] = (e0 + e1) + (e2 + e3);
        }
        __syncthreads();
        // j-side flush for this half (off-diagonal tiles only)
        if (gi != gj) {
#pragma unroll
            for (int w = 0; w < 2; w++) {
                int cell = t + w * 512;           // 0..1023
                int jj = cell >> 6;
                int bb = cell & 63;
                float s = red[jj][0][bb] + red[jj][1][bb] + red[jj][2][bb] + red[jj][3][bb]
                        + red[jj][4][bb] + red[jj][5][bb] + red[jj][6][bb] + red[jj][7][bb];
                atomicAdd(out + (size_t)(j0 + half * 16 + jj) * OUTW + AA + bb, s);
            }
        }
        __syncthreads();
    }

    // i-side: atomic add per owned row
#pragma unroll
    for (int k = 0; k < 4; k++)
        atomicAdd(out + (size_t)(i0 + k) * OUTW + AA + b, acc_i[k]);
}

// ---------------------------------------------------------------------------
extern "C" void kernel_launch(void* const* d_in, const int* in_sizes, int n_in,
                              void* d_out, int out_size) {
    const float* x = (const float*)d_in[0];   // (512, 1024)
    const float* T = (const float*)d_in[1];   // (1024, 1024)
    float* out = (float*)d_out;               // (512, 1088)

    dim3 ggrid(AA / 64, NN / 64);             // (16, 8) = 128 blocks
    gemm_fused_kernel<<<ggrid, 128>>>(x, T, out);

    pairwise_kernel<<<NTILES, 512>>>(out);    // 136 blocks, single wave
}